// round 6
// baseline (speedup 1.0000x reference)
#include <cuda_runtime.h>
#include <cstdint>

// Problem constants (match reference)
#define NUM_MOVABLE 10000000
#define NUM_PHYS    11000000
#define BXD 32
#define BYD 32
#define NBINS (BXD * BYD)

#define HIST_BLOCKS 592   // 4 CTAs/SM on 148 SMs
#define HIST_THREADS 256

// Global scratch accumulators (no cudaMalloc allowed).
// Fixed-point units of 1/512. gA = S(low32) | Sx(high32); gB = Sy | Sxy.
__device__ unsigned long long gA[NBINS];
__device__ unsigned long long gB[NBINS];

__global__ void zero_kernel() {
    gA[threadIdx.x] = 0ull;
    gB[threadIdx.x] = 0ull;
}

// Per element: fx = clip(x*32, 0, 31-1e-6); ix = floor(fx); dx = fx - ix.
// Moments at source bin (iy,ix):  S += a, Sx += a*dx, Sy += a*dy, Sxy += a*dx*dy.
// density(j,i) = (S-Sx-Sy+Sxy)[j,i] + (Sx-Sxy)[j,i-1] + (Sy-Sxy)[j-1,i] + Sxy[j-1,i-1].
__device__ __forceinline__ unsigned long long make_packed(
        float x, float y, float sx, float sy, int m) {
    const float CLMP = 30.9999990463f;          // float(31 - 1e-6)
    const float MAGIC = 8388608.0f;             // 2^23  (RNE-to-integer trick)

    float fx = fminf(fmaxf(x * 32.0f, 0.0f), CLMP);
    float fy = fminf(fmaxf(y * 32.0f, 0.0f), CLMP);

    // q = round(f * 65536), exact FMA product + single RNE rounding.
    unsigned qx = __float_as_uint(fmaf(fx, 65536.0f, MAGIC)) & 0x3FFFFF;
    unsigned qy = __float_as_uint(fmaf(fy, 65536.0f, MAGIC)) & 0x3FFFFF;

    float a = fminf(sx * 32.0f, 1.0f) * fminf(sy * 32.0f, 1.0f);
    if (m == 0) a = 0.0f;
    unsigned a512 = __float_as_uint(fmaf(a, 512.0f, MAGIC)) & 0xFFFF;  // round(a*512) <= 512

    unsigned dxq = qx & 0xFFFFu;                // dx in 2^-16 units
    unsigned dyq = qy & 0xFFFFu;
    unsigned ix  = qx >> 16;                    // 0..31
    unsigned iy  = qy >> 16;

    unsigned adx  = (a512 * dxq + 32768u) >> 16;   // round(a*dx*512) <= 512
    unsigned ady  = (a512 * dyq + 32768u) >> 16;
    unsigned adxy = (adx  * dyq + 32768u) >> 16;

    unsigned lo = a512 | (adx << 16);
    unsigned hi = ady  | (adxy << 16);
    unsigned long long v = (unsigned long long)lo |
                           ((unsigned long long)hi << 32);
    // caller needs bin too: encode via separate return? keep inline below instead.
    return v | ((unsigned long long)0);  // value only; bin computed by caller from qx,qy
}

__global__ void __launch_bounds__(HIST_THREADS)
hist_kernel(const float4* __restrict__ x4,
            const float4* __restrict__ y4,
            const int4*   __restrict__ m4,    // mask is int32 per element
            const float4* __restrict__ sx4,
            const float4* __restrict__ sy4) {
    __shared__ unsigned long long sh[NBINS];   // 4x16-bit fields: S,adx,ady,adxy (1/512 units)
    for (int i = threadIdx.x; i < NBINS; i += HIST_THREADS) sh[i] = 0ull;
    __syncthreads();

    const float CLMP  = 30.9999990463f;
    const float MAGIC = 8388608.0f;

    const int n4 = NUM_MOVABLE / 4;            // 2,500,000 exact
    for (int i = blockIdx.x * HIST_THREADS + threadIdx.x; i < n4;
         i += gridDim.x * HIST_THREADS) {
        float4 x  = __ldg(x4  + i);
        float4 y  = __ldg(y4  + i);
        float4 sx = __ldg(sx4 + i);
        float4 sy = __ldg(sy4 + i);
        int4   m  = __ldg(m4  + i);

        #pragma unroll
        for (int k = 0; k < 4; k++) {
            float xv  = (k == 0) ? x.x  : (k == 1) ? x.y  : (k == 2) ? x.z  : x.w;
            float yv  = (k == 0) ? y.x  : (k == 1) ? y.y  : (k == 2) ? y.z  : y.w;
            float sxv = (k == 0) ? sx.x : (k == 1) ? sx.y : (k == 2) ? sx.z : sx.w;
            float syv = (k == 0) ? sy.x : (k == 1) ? sy.y : (k == 2) ? sy.z : sy.w;
            int   mv  = (k == 0) ? m.x  : (k == 1) ? m.y  : (k == 2) ? m.z  : m.w;

            float fx = fminf(fmaxf(xv * 32.0f, 0.0f), CLMP);
            float fy = fminf(fmaxf(yv * 32.0f, 0.0f), CLMP);
            unsigned qx = __float_as_uint(fmaf(fx, 65536.0f, MAGIC)) & 0x3FFFFF;
            unsigned qy = __float_as_uint(fmaf(fy, 65536.0f, MAGIC)) & 0x3FFFFF;

            float a = fminf(sxv * 32.0f, 1.0f) * fminf(syv * 32.0f, 1.0f);
            if (mv == 0) a = 0.0f;
            unsigned a512 = __float_as_uint(fmaf(a, 512.0f, MAGIC)) & 0xFFFF;

            unsigned dxq = qx & 0xFFFFu;
            unsigned dyq = qy & 0xFFFFu;
            unsigned ix  = qx >> 16;
            unsigned iy  = qy >> 16;

            unsigned adx  = (a512 * dxq + 32768u) >> 16;
            unsigned ady  = (a512 * dyq + 32768u) >> 16;
            unsigned adxy = (adx  * dyq + 32768u) >> 16;

            unsigned long long v =
                (unsigned long long)(a512 | (adx << 16)) |
                ((unsigned long long)(ady | (adxy << 16)) << 32);

            atomicAdd(&sh[iy * BXD + ix], v);
        }
    }
    __syncthreads();

    // Flush: widen 16-bit fields to 32-bit, 2 u64 global atomics per bin.
    // Global per-field totals <= ~2e7 << 2^32: no cross-field carry.
    for (int i = threadIdx.x; i < NBINS; i += HIST_THREADS) {
        unsigned long long v = sh[i];
        if (v != 0ull) {
            unsigned long long A = (v & 0xFFFFull) |
                                   (((v >> 16) & 0xFFFFull) << 32);
            unsigned long long B = ((v >> 32) & 0xFFFFull) |
                                   (((v >> 48) & 0xFFFFull) << 32);
            atomicAdd(&gA[i], A);
            atomicAdd(&gB[i], B);
        }
    }
}

__global__ void __launch_bounds__(NBINS)
var_kernel(float* __restrict__ out) {
    __shared__ float C00[NBINS], CX[NBINS], CY[NBINS], CXY[NBINS];
    __shared__ float red[32];
    __shared__ float mean_sh;

    int t    = threadIdx.x;
    int lane = t & 31;
    int wid  = t >> 5;

    unsigned long long A = gA[t];
    unsigned long long B = gB[t];
    const float inv = 1.0f / 512.0f;
    float S   = (float)(unsigned)(A & 0xFFFFFFFFull) * inv;
    float Sx  = (float)(unsigned)(A >> 32)           * inv;
    float Sy  = (float)(unsigned)(B & 0xFFFFFFFFull) * inv;
    float Sxy = (float)(unsigned)(B >> 32)           * inv;

    C00[t] = S - Sx - Sy + Sxy;
    CX [t] = Sx - Sxy;
    CY [t] = Sy - Sxy;
    CXY[t] = Sxy;
    __syncthreads();

    int i = t & 31, j = t >> 5;
    float v = C00[t];
    if (i > 0)          v += CX [t - 1];
    if (j > 0)          v += CY [t - 32];
    if (i > 0 && j > 0) v += CXY[t - 33];

    // mean
    float s = v;
    #pragma unroll
    for (int off = 16; off > 0; off >>= 1)
        s += __shfl_xor_sync(0xFFFFFFFFu, s, off);
    if (lane == 0) red[wid] = s;
    __syncthreads();
    if (t < 32) {
        float s2 = red[t];
        #pragma unroll
        for (int off = 16; off > 0; off >>= 1)
            s2 += __shfl_xor_sync(0xFFFFFFFFu, s2, off);
        if (t == 0) mean_sh = s2 * (1.0f / (float)NBINS);
    }
    __syncthreads();

    // sum of squared deviations
    float d = v - mean_sh;
    float q = d * d;
    #pragma unroll
    for (int off = 16; off > 0; off >>= 1)
        q += __shfl_xor_sync(0xFFFFFFFFu, q, off);
    __syncthreads();
    if (lane == 0) red[wid] = q;
    __syncthreads();
    if (t < 32) {
        float q2 = red[t];
        #pragma unroll
        for (int off = 16; off > 0; off >>= 1)
            q2 += __shfl_xor_sync(0xFFFFFFFFu, q2, off);
        if (t == 0) out[0] = q2 * (1.0f / (float)(NBINS - 1));  // ddof=1
    }
}

extern "C" void kernel_launch(void* const* d_in, const int* in_sizes, int n_in,
                              void* d_out, int out_size) {
    const float* pos  = (const float*)d_in[0];
    const int*   mask = (const int*)d_in[1];      // jax bool -> int32 in harness
    const float* msx  = (const float*)d_in[2];
    const float* msy  = (const float*)d_in[3];

    const float4* x4  = (const float4*)(pos);               // pos[0 : 10M)
    const float4* y4  = (const float4*)(pos + NUM_PHYS);    // pos[11M : 21M), 16B aligned
    const int4*   m4  = (const int4*)(mask);
    const float4* sx4 = (const float4*)(msx);
    const float4* sy4 = (const float4*)(msy);

    zero_kernel<<<1, NBINS>>>();
    hist_kernel<<<HIST_BLOCKS, HIST_THREADS>>>(x4, y4, m4, sx4, sy4);
    var_kernel<<<1, NBINS>>>((float*)d_out);
}